// round 12
// baseline (speedup 1.0000x reference)
#include <cuda_runtime.h>
#include <cuda_fp16.h>
#include <cstdint>

#define NN      50000
#define E_RSR   3000000
#define E_RTR   1000000
#define E_RUR   200000
#define E_TOT   4200000
#define NROWS   (3 * NN)
// padded per-(rel,dst) buckets, node-major: row base = dst*256 + OFF[r]
#define CAP0    160     // rel0 in-deg lambda=60
#define CAP1    64      // rel1 lambda=20
#define CAP2    32      // rel2 lambda=4
#define CAPT    256
#define NB_T    196     // ceil(NN/256) transform blocks

// ---------------- device scratch ----------------
__device__ int            g_deg_out[NROWS];
__device__ int            g_cnt[NROWS];              // in-degree counters / row lengths
__device__ unsigned short g_ssrc[(size_t)NN * CAPT]; // bucketed src ids (25.6MB)
__device__ __half         g_hrh[3][NN * 16];         // fp16 pre-aggregation features
__device__ float          g_gv[NROWS];
__device__ int            g_is64;

// ---------------- helpers ----------------
__device__ __forceinline__ int4 ldcs_i4(const void* p) {
    int4 v;
    asm volatile("ld.global.cs.v4.b32 {%0,%1,%2,%3}, [%4];"
                 : "=r"(v.x), "=r"(v.y), "=r"(v.z), "=r"(v.w) : "l"(p));
    return v;
}
__device__ __forceinline__ int2 ldcs_i2(const void* p) {
    int2 v;
    asm volatile("ld.global.cs.v2.b32 {%0,%1}, [%2];" : "=r"(v.x), "=r"(v.y) : "l"(p));
    return v;
}
__device__ __forceinline__ float rinv_of(int deg) {
    return rsqrtf(fmaxf((float)deg, 1.f));
}

// ---------------- init: zero counters + dtype probe ----------------
__global__ void k_init(const unsigned* p) {
    int i = blockIdx.x * blockDim.x + threadIdx.x;
    if (i == 0) {
        int all0 = 1;
        #pragma unroll 1
        for (int k = 0; k < 64; k++)
            if (p[2 * k + 1] != 0u) { all0 = 0; break; }
        g_is64 = all0;
    }
    if (i < NROWS) { g_deg_out[i] = 0; g_cnt[i] = 0; }
}

// ---------------- single edge pass: deg_out RED + bucket scatter (2 edges/thread) ----------------
__global__ void __launch_bounds__(256) k_pass1(const void* s0, const void* d0,
                                               const void* s1, const void* d1,
                                               const void* s2, const void* d2) {
    int t = blockIdx.x * blockDim.x + threadIdx.x;
    int i = t * 2;
    if (i >= E_TOT) return;
    int r, e, off;
    const void *sp, *dp;
    if (i < E_RSR)                { r = 0; e = i;                 sp = s0; dp = d0; off = 0; }
    else if (i < E_RSR + E_RTR)   { r = 1; e = i - E_RSR;         sp = s1; dp = d1; off = CAP0; }
    else                          { r = 2; e = i - E_RSR - E_RTR; sp = s2; dp = d2; off = CAP0 + CAP1; }
    int sA, sB, dA, dB;
    if (g_is64) {
        int4 sv = ldcs_i4((const char*)sp + (size_t)e * 8);
        int4 dv = ldcs_i4((const char*)dp + (size_t)e * 8);
        sA = sv.x; sB = sv.z; dA = dv.x; dB = dv.z;
    } else {
        int2 sv = ldcs_i2((const char*)sp + (size_t)e * 4);
        int2 dv = ldcs_i2((const char*)dp + (size_t)e * 4);
        sA = sv.x; sB = sv.y; dA = dv.x; dB = dv.y;
    }
    int rb = r * NN;
    atomicAdd(&g_deg_out[rb + sA], 1);
    atomicAdd(&g_deg_out[rb + sB], 1);
    int pA = atomicAdd(&g_cnt[rb + dA], 1);
    int pB = atomicAdd(&g_cnt[rb + dB], 1);
    g_ssrc[(size_t)dA * CAPT + off + pA] = (unsigned short)sA;
    g_ssrc[(size_t)dB * CAPT + off + pB] = (unsigned short)sB;
}

// ---------------- layer-1 transform -> fp16, smem-staged coalesced x ----------------
__global__ void __launch_bounds__(256) k_transform1(const float* __restrict__ x,
                                                    const float* __restrict__ W1) {
    __shared__ float sW[3 * 32 * 16];
    __shared__ float sx[256 * 33];           // pad 33 -> conflict-free row reads
    for (int j = threadIdx.x; j < 1536; j += 256) sW[j] = W1[j];
    int nbase = blockIdx.x * 256;
    // coalesced stage of up to 256 x-rows
    for (int j = threadIdx.x; j < 256 * 32; j += 256) {
        int node = j >> 5, c = j & 31;
        int gidx = nbase * 32 + j;
        if (nbase + node < NN) sx[node * 33 + c] = x[gidx];
    }
    __syncthreads();
    int n = nbase + threadIdx.x;
    if (n >= NN) return;
    const float* xr = &sx[threadIdx.x * 33];
    #pragma unroll 1
    for (int r = 0; r < 3; r++) {
        float rv = rinv_of(g_deg_out[r * NN + n]);
        float o[16];
        #pragma unroll
        for (int j = 0; j < 16; j++) o[j] = 0.f;
        const float* wr = &sW[r * 512];
        #pragma unroll
        for (int k = 0; k < 32; k++) {
            float xk = xr[k];
            const float* w = wr + k * 16;
            #pragma unroll
            for (int j = 0; j < 16; j++) o[j] = fmaf(xk, w[j], o[j]);
        }
        uint4 pk[2];
        unsigned* pw = (unsigned*)pk;
        #pragma unroll
        for (int q = 0; q < 8; q++) {
            __half2 h = __floats2half2_rn(o[2 * q] * rv, o[2 * q + 1] * rv);
            pw[q] = *(unsigned*)&h;
        }
        uint4* hp = (uint4*)&g_hrh[r][n * 16];
        hp[0] = pk[0];
        hp[1] = pk[1];
    }
}

// ---------------- gather layer 1: lane-per-edge (fused relu + bias + W2 projection) ----------------
__global__ void __launch_bounds__(256) k_gather1(const float* __restrict__ b1,
                                                 const float* __restrict__ W2) {
    int wid = (blockIdx.x * blockDim.x + threadIdx.x) >> 5;
    if (wid >= NN) return;
    int lane = threadIdx.x & 31;
    const int offs[3] = { 0, CAP0, CAP0 + CAP1 };
    int cnt[3];
    #pragma unroll
    for (int r = 0; r < 3; r++) cnt[r] = __ldg(&g_cnt[r * NN + wid]);
    const unsigned short* row = &g_ssrc[(size_t)wid * CAPT];
    float acc[16];
    #pragma unroll
    for (int k = 0; k < 16; k++) acc[k] = 0.f;
    #pragma unroll
    for (int r = 0; r < 3; r++) {
        int st = offs[r];
        int end = st + cnt[r];
        float w = rinv_of(cnt[r]);
        const __half* hr = g_hrh[r];
        for (int base = st; base < end; base += 32) {
            int eid = base + lane;
            if (eid < end) {
                int s = (int)__ldg(&row[eid]);       // coalesced u16 load
                const uint4* hp = (const uint4*)&hr[s * 16];
                uint4 u0 = __ldg(hp);
                uint4 u1 = __ldg(hp + 1);
                const unsigned* uw = (const unsigned*)&u0;
                #pragma unroll
                for (int q = 0; q < 4; q++) {
                    float2 f = __half22float2(*(const __half2*)&uw[q]);
                    acc[2 * q]     = fmaf(f.x, w, acc[2 * q]);
                    acc[2 * q + 1] = fmaf(f.y, w, acc[2 * q + 1]);
                }
                const unsigned* vw = (const unsigned*)&u1;
                #pragma unroll
                for (int q = 0; q < 4; q++) {
                    float2 f = __half22float2(*(const __half2*)&vw[q]);
                    acc[8 + 2 * q]     = fmaf(f.x, w, acc[8 + 2 * q]);
                    acc[8 + 2 * q + 1] = fmaf(f.y, w, acc[8 + 2 * q + 1]);
                }
            }
        }
    }
    // butterfly-reduce all 16 accumulators across the warp (all lanes end with full h)
    #pragma unroll
    for (int m = 16; m >= 1; m >>= 1) {
        #pragma unroll
        for (int k = 0; k < 16; k++)
            acc[k] += __shfl_xor_sync(0xffffffffu, acc[k], m);
    }
    // bias (summed over relations) + relu
    #pragma unroll
    for (int k = 0; k < 16; k++) {
        float bs = __ldg(&b1[k]) + __ldg(&b1[16 + k]) + __ldg(&b1[32 + k]);
        acc[k] = fmaxf(acc[k] + bs, 0.f);
    }
    // layer-2 projection per relation (lanes 0..2 write)
    if (lane < 3) {
        int r = lane;
        const float* w2 = W2 + r * 16;
        float p = 0.f;
        #pragma unroll
        for (int k = 0; k < 16; k++) p = fmaf(acc[k], __ldg(&w2[k]), p);
        g_gv[r * NN + wid] = p * rinv_of(__ldg(&g_deg_out[r * NN + wid]));
    }
}

// ---------------- gather layer 2 ----------------
__global__ void __launch_bounds__(256) k_gather2(float* __restrict__ out,
                                                 const float* __restrict__ b2) {
    int wid = (blockIdx.x * blockDim.x + threadIdx.x) >> 5;
    if (wid >= NN) return;
    int lane = threadIdx.x & 31;
    const int offs[3] = { 0, CAP0, CAP0 + CAP1 };
    int cnt[3];
    #pragma unroll
    for (int r = 0; r < 3; r++) cnt[r] = __ldg(&g_cnt[r * NN + wid]);
    const unsigned short* row = &g_ssrc[(size_t)wid * CAPT];
    float sum = 0.f;
    #pragma unroll
    for (int r = 0; r < 3; r++) {
        int st = offs[r];
        int end = st + cnt[r];
        float w = rinv_of(cnt[r]);
        const float* gv = &g_gv[r * NN];
        for (int base = st; base < end; base += 32) {
            int eid = base + lane;
            if (eid < end) {
                int s = (int)__ldg(&row[eid]);
                sum = fmaf(__ldg(&gv[s]), w, sum);
            }
        }
    }
    #pragma unroll
    for (int m = 16; m >= 1; m >>= 1)
        sum += __shfl_xor_sync(0xffffffffu, sum, m);
    if (lane == 0)
        out[wid] = sum + __ldg(&b2[0]) + __ldg(&b2[1]) + __ldg(&b2[2]);
}

// =====================================================================================
extern "C" void kernel_launch(void* const* d_in, const int* in_sizes, int n_in,
                              void* d_out, int out_size) {
    const float* x  = (const float*)d_in[0];
    const void*  s0 = d_in[1]; const void* d0 = d_in[2];
    const void*  s1 = d_in[3]; const void* d1 = d_in[4];
    const void*  s2 = d_in[5]; const void* d2 = d_in[6];
    const float* W1 = (const float*)d_in[7];
    const float* b1 = (const float*)d_in[8];
    const float* W2 = (const float*)d_in[9];
    const float* b2 = (const float*)d_in[10];
    float* out = (float*)d_out;

    k_init      <<<(NROWS + 255) / 256, 256>>>((const unsigned*)s0);            // 0
    k_pass1     <<<(E_TOT / 2 + 255) / 256, 256>>>(s0, d0, s1, d1, s2, d2);     // 1
    k_transform1<<<NB_T, 256>>>(x, W1);                                         // 2
    k_gather1   <<<(NN * 32 + 255) / 256, 256>>>(b1, W2);                       // 3 <- profiled
    k_gather2   <<<(NN * 32 + 255) / 256, 256>>>(out, b2);                      // 4
}

// round 13
// speedup vs baseline: 1.1264x; 1.1264x over previous
#include <cuda_runtime.h>
#include <cuda_fp16.h>
#include <cstdint>

#define NN      50000
#define E_RSR   3000000
#define E_RTR   1000000
#define E_RUR   200000
#define E_TOT   4200000
#define NROWS   (3 * NN)
// padded per-(rel,dst) buckets, node-major: row base = dst*256 + OFF[r]
#define CAP0    160     // rel0 in-deg lambda=60
#define CAP1    64      // rel1 lambda=20
#define CAP2    32      // rel2 lambda=4
#define CAPT    256
#define NB_T    196     // ceil(NN/256) transform blocks

// ---------------- device scratch ----------------
__device__ int            g_deg_out[NROWS];
__device__ int            g_cnt[NROWS];              // in-degree counters / row lengths
__device__ unsigned short g_ssrc[(size_t)NN * CAPT]; // bucketed src ids (25.6MB)
__device__ __half         g_hrh[3][NN * 16];         // fp16 pre-aggregation features
__device__ float          g_gv[NROWS];
__device__ int            g_is64;

// ---------------- helpers ----------------
__device__ __forceinline__ int4 ldcs_i4(const void* p) {
    int4 v;
    asm volatile("ld.global.cs.v4.b32 {%0,%1,%2,%3}, [%4];"
                 : "=r"(v.x), "=r"(v.y), "=r"(v.z), "=r"(v.w) : "l"(p));
    return v;
}
__device__ __forceinline__ int2 ldcs_i2(const void* p) {
    int2 v;
    asm volatile("ld.global.cs.v2.b32 {%0,%1}, [%2];" : "=r"(v.x), "=r"(v.y) : "l"(p));
    return v;
}
__device__ __forceinline__ float rinv_of(int deg) {
    return rsqrtf(fmaxf((float)deg, 1.f));
}

// ---------------- init: zero counters + dtype probe ----------------
__global__ void k_init(const unsigned* p) {
    int i = blockIdx.x * blockDim.x + threadIdx.x;
    if (i == 0) {
        int all0 = 1;
        #pragma unroll 1
        for (int k = 0; k < 64; k++)
            if (p[2 * k + 1] != 0u) { all0 = 0; break; }
        g_is64 = all0;
    }
    if (i < NROWS) { g_deg_out[i] = 0; g_cnt[i] = 0; }
}

// ---------------- single edge pass: deg_out RED + bucket scatter (2 edges/thread) ----------------
__global__ void __launch_bounds__(256) k_pass1(const void* s0, const void* d0,
                                               const void* s1, const void* d1,
                                               const void* s2, const void* d2) {
    int t = blockIdx.x * blockDim.x + threadIdx.x;
    int i = t * 2;
    if (i >= E_TOT) return;
    int r, e, off;
    const void *sp, *dp;
    if (i < E_RSR)                { r = 0; e = i;                 sp = s0; dp = d0; off = 0; }
    else if (i < E_RSR + E_RTR)   { r = 1; e = i - E_RSR;         sp = s1; dp = d1; off = CAP0; }
    else                          { r = 2; e = i - E_RSR - E_RTR; sp = s2; dp = d2; off = CAP0 + CAP1; }
    int sA, sB, dA, dB;
    if (g_is64) {
        int4 sv = ldcs_i4((const char*)sp + (size_t)e * 8);
        int4 dv = ldcs_i4((const char*)dp + (size_t)e * 8);
        sA = sv.x; sB = sv.z; dA = dv.x; dB = dv.z;
    } else {
        int2 sv = ldcs_i2((const char*)sp + (size_t)e * 4);
        int2 dv = ldcs_i2((const char*)dp + (size_t)e * 4);
        sA = sv.x; sB = sv.y; dA = dv.x; dB = dv.y;
    }
    int rb = r * NN;
    atomicAdd(&g_deg_out[rb + sA], 1);
    atomicAdd(&g_deg_out[rb + sB], 1);
    int pA = atomicAdd(&g_cnt[rb + dA], 1);
    int pB = atomicAdd(&g_cnt[rb + dB], 1);
    g_ssrc[(size_t)dA * CAPT + off + pA] = (unsigned short)sA;
    g_ssrc[(size_t)dB * CAPT + off + pB] = (unsigned short)sB;
}

// ---------------- layer-1 transform -> fp16, smem-staged coalesced x ----------------
__global__ void __launch_bounds__(256) k_transform1(const float* __restrict__ x,
                                                    const float* __restrict__ W1) {
    __shared__ float sW[3 * 32 * 16];
    __shared__ float sx[256 * 33];           // pad 33 -> conflict-free row reads
    for (int j = threadIdx.x; j < 1536; j += 256) sW[j] = W1[j];
    int nbase = blockIdx.x * 256;
    for (int j = threadIdx.x; j < 256 * 32; j += 256) {
        int node = j >> 5, c = j & 31;
        int gidx = nbase * 32 + j;
        if (nbase + node < NN) sx[node * 33 + c] = x[gidx];
    }
    __syncthreads();
    int n = nbase + threadIdx.x;
    if (n >= NN) return;
    const float* xr = &sx[threadIdx.x * 33];
    #pragma unroll 1
    for (int r = 0; r < 3; r++) {
        float rv = rinv_of(g_deg_out[r * NN + n]);
        float o[16];
        #pragma unroll
        for (int j = 0; j < 16; j++) o[j] = 0.f;
        const float* wr = &sW[r * 512];
        #pragma unroll
        for (int k = 0; k < 32; k++) {
            float xk = xr[k];
            const float* w = wr + k * 16;
            #pragma unroll
            for (int j = 0; j < 16; j++) o[j] = fmaf(xk, w[j], o[j]);
        }
        uint4 pk[2];
        unsigned* pw = (unsigned*)pk;
        #pragma unroll
        for (int q = 0; q < 8; q++) {
            __half2 h = __floats2half2_rn(o[2 * q] * rv, o[2 * q + 1] * rv);
            pw[q] = *(unsigned*)&h;
        }
        uint4* hp = (uint4*)&g_hrh[r][n * 16];
        hp[0] = pk[0];
        hp[1] = pk[1];
    }
}

// ---------------- gather layer 1: 2 lanes per edge (uint4), fused relu+bias+W2 ----------------
// lane = slot*2 + chunk; slot in [0,16) = edge within group, chunk in {0,1} = 16B half of row.
// One feature-load instruction covers 16 edges (16 lines) -> 1 wavefront/edge, ~1.6 instr/edge.
__global__ void __launch_bounds__(256) k_gather1(const float* __restrict__ b1,
                                                 const float* __restrict__ W2) {
    int wid = (blockIdx.x * blockDim.x + threadIdx.x) >> 5;
    if (wid >= NN) return;
    int lane = threadIdx.x & 31;
    int slot = lane >> 1, chunk = lane & 1;
    const int offs[3] = { 0, CAP0, CAP0 + CAP1 };
    int cnt[3];
    #pragma unroll
    for (int r = 0; r < 3; r++) cnt[r] = __ldg(&g_cnt[r * NN + wid]);
    const unsigned short* row = &g_ssrc[(size_t)wid * CAPT];
    float acc[8];
    #pragma unroll
    for (int k = 0; k < 8; k++) acc[k] = 0.f;
    #pragma unroll
    for (int r = 0; r < 3; r++) {
        int st = offs[r];
        int end = st + cnt[r];
        float w = rinv_of(cnt[r]);
        const __half* hr = g_hrh[r];
        for (int base = st; base < end; base += 16) {
            int eid = base + slot;
            if (eid < end) {
                int s = (int)__ldg(&row[eid]);                       // 16 distinct u16 / warp
                uint4 u = __ldg((const uint4*)&hr[s * 16 + chunk * 8]); // 16B half-row
                const unsigned* uw = (const unsigned*)&u;
                #pragma unroll
                for (int q = 0; q < 4; q++) {
                    float2 f = __half22float2(*(const __half2*)&uw[q]);
                    acc[2 * q]     = fmaf(f.x, w, acc[2 * q]);
                    acc[2 * q + 1] = fmaf(f.y, w, acc[2 * q + 1]);
                }
            }
        }
    }
    // reduce across the 16 slots (keep chunk): masks 2,4,8,16
    #pragma unroll
    for (int m = 2; m <= 16; m <<= 1) {
        #pragma unroll
        for (int k = 0; k < 8; k++)
            acc[k] += __shfl_xor_sync(0xffffffffu, acc[k], m);
    }
    // bias (summed over relations) + relu; this lane holds features chunk*8 .. chunk*8+7
    int c8 = chunk * 8;
    #pragma unroll
    for (int k = 0; k < 8; k++) {
        float bs = __ldg(&b1[c8 + k]) + __ldg(&b1[16 + c8 + k]) + __ldg(&b1[32 + c8 + k]);
        acc[k] = fmaxf(acc[k] + bs, 0.f);
    }
    // layer-2 projection per relation: partial dot over this half, combine via xor-1
    #pragma unroll
    for (int r = 0; r < 3; r++) {
        const float* w2 = W2 + r * 16 + c8;
        float p = 0.f;
        #pragma unroll
        for (int k = 0; k < 8; k++) p = fmaf(acc[k], __ldg(&w2[k]), p);
        p += __shfl_xor_sync(0xffffffffu, p, 1);    // full 16-dot on both chunk lanes
        if (lane == r)
            g_gv[r * NN + wid] = p * rinv_of(__ldg(&g_deg_out[r * NN + wid]));
    }
}

// ---------------- gather layer 2 (pipelined, R11 shape) ----------------
__global__ void __launch_bounds__(256) k_gather2(float* __restrict__ out,
                                                 const float* __restrict__ b2) {
    int wid = (blockIdx.x * blockDim.x + threadIdx.x) >> 5;
    if (wid >= NN) return;
    int lane = threadIdx.x & 31;
    const int offs[3] = { 0, CAP0, CAP0 + CAP1 };
    int cnt[3];
    #pragma unroll
    for (int r = 0; r < 3; r++) cnt[r] = __ldg(&g_cnt[r * NN + wid]);
    const unsigned short* row = &g_ssrc[(size_t)wid * CAPT];
    float sum = 0.f;
    #pragma unroll
    for (int r = 0; r < 3; r++) {
        int st = offs[r];
        int end = st + cnt[r];
        float w = rinv_of(cnt[r]);
        const float* gv = &g_gv[r * NN];
        int base = st;
        int eid = base + lane;
        int sCur = (eid < end) ? (int)__ldg(&row[eid]) : 0;
        for (; base < end; base += 32) {
            bool valid = (base + lane) < end;
            int s = sCur;
            int ne = base + 32 + lane;
            sCur = (ne < end) ? (int)__ldg(&row[ne]) : 0;
            if (valid) sum = fmaf(__ldg(&gv[s]), w, sum);
        }
    }
    #pragma unroll
    for (int m = 16; m >= 1; m >>= 1)
        sum += __shfl_xor_sync(0xffffffffu, sum, m);
    if (lane == 0)
        out[wid] = sum + __ldg(&b2[0]) + __ldg(&b2[1]) + __ldg(&b2[2]);
}

// =====================================================================================
extern "C" void kernel_launch(void* const* d_in, const int* in_sizes, int n_in,
                              void* d_out, int out_size) {
    const float* x  = (const float*)d_in[0];
    const void*  s0 = d_in[1]; const void* d0 = d_in[2];
    const void*  s1 = d_in[3]; const void* d1 = d_in[4];
    const void*  s2 = d_in[5]; const void* d2 = d_in[6];
    const float* W1 = (const float*)d_in[7];
    const float* b1 = (const float*)d_in[8];
    const float* W2 = (const float*)d_in[9];
    const float* b2 = (const float*)d_in[10];
    float* out = (float*)d_out;

    k_init      <<<(NROWS + 255) / 256, 256>>>((const unsigned*)s0);            // 0
    k_pass1     <<<(E_TOT / 2 + 255) / 256, 256>>>(s0, d0, s1, d1, s2, d2);     // 1
    k_transform1<<<NB_T, 256>>>(x, W1);                                         // 2
    k_gather1   <<<(NN * 32 + 255) / 256, 256>>>(b1, W2);                       // 3 <- profiled
    k_gather2   <<<(NN * 32 + 255) / 256, 256>>>(out, b2);                      // 4
}

// round 14
// speedup vs baseline: 1.2317x; 1.0935x over previous
#include <cuda_runtime.h>
#include <cuda_fp16.h>
#include <cstdint>

#define NN      50000
#define E_RSR   3000000
#define E_RTR   1000000
#define E_RUR   200000
#define E_TOT   4200000
#define NROWS   (3 * NN)
// padded per-(rel,dst) buckets, node-major: row base = dst*256 + OFF[r]
#define CAP0    160     // rel0 in-deg lambda=60
#define CAP1    64      // rel1 lambda=20
#define CAP2    32      // rel2 lambda=4
#define CAPT    256
#define NB_T    196     // ceil(NN/256) transform blocks in fused kernel
#define NB_SCAT ((E_TOT / 2 + 255) / 256)   // 8204 scatter blocks

// ---------------- device scratch ----------------
__device__ int            g_deg_out[NROWS];
__device__ int            g_cnt[NROWS];              // in-degree counters / row lengths
__device__ unsigned short g_ssrc[(size_t)NN * CAPT]; // bucketed src ids (25.6MB)
__device__ __half         g_hrh[3][NN * 16];         // fp16 features (unscaled until k_scale)
__device__ float          g_gv[NROWS];
__device__ int            g_is64;

// ---------------- helpers ----------------
__device__ __forceinline__ int4 ldcs_i4(const void* p) {
    int4 v;
    asm volatile("ld.global.cs.v4.b32 {%0,%1,%2,%3}, [%4];"
                 : "=r"(v.x), "=r"(v.y), "=r"(v.z), "=r"(v.w) : "l"(p));
    return v;
}
__device__ __forceinline__ int2 ldcs_i2(const void* p) {
    int2 v;
    asm volatile("ld.global.cs.v2.b32 {%0,%1}, [%2];" : "=r"(v.x), "=r"(v.y) : "l"(p));
    return v;
}
__device__ __forceinline__ float rinv_of(int deg) {
    return rsqrtf(fmaxf((float)deg, 1.f));
}

// ---------------- init: zero counters + dtype probe ----------------
__global__ void k_init(const unsigned* p) {
    int i = blockIdx.x * blockDim.x + threadIdx.x;
    if (i == 0) {
        int all0 = 1;
        #pragma unroll 1
        for (int k = 0; k < 64; k++)
            if (p[2 * k + 1] != 0u) { all0 = 0; break; }
        g_is64 = all0;
    }
    if (i < NROWS) { g_deg_out[i] = 0; g_cnt[i] = 0; }
}

// ---------------- fused pass1: matmul transform (blocks [0,NB_T)) + edge pass ----------------
// transform path has NO dependency on the edge pass (stores UNSCALED fp16 features);
// scaling by rsqrt(deg_out) happens in k_scale after this kernel completes.
__global__ void __launch_bounds__(256, 6) k_pass1(
        const float* __restrict__ x, const float* __restrict__ W1,
        const void* s0, const void* d0,
        const void* s1, const void* d1,
        const void* s2, const void* d2) {
    if (blockIdx.x < NB_T) {
        // ---- matmul path: stream x in float4 chunks (low reg pressure) ----
        __shared__ float sW[3 * 32 * 16];
        for (int j = threadIdx.x; j < 1536; j += 256) sW[j] = W1[j];
        __syncthreads();
        int n = blockIdx.x * 256 + threadIdx.x;
        if (n >= NN) return;
        const float4* xp = (const float4*)(x + (size_t)n * 32);
        #pragma unroll 1
        for (int r = 0; r < 3; r++) {
            float o[16];
            #pragma unroll
            for (int j = 0; j < 16; j++) o[j] = 0.f;
            const float* wr = &sW[r * 512];
            #pragma unroll
            for (int q = 0; q < 8; q++) {
                float4 v = __ldg(&xp[q]);           // L1-hot after first relation
                const float* w = wr + q * 64;
                #pragma unroll
                for (int j = 0; j < 16; j++) o[j] = fmaf(v.x, w[j], o[j]);
                #pragma unroll
                for (int j = 0; j < 16; j++) o[j] = fmaf(v.y, w[16 + j], o[j]);
                #pragma unroll
                for (int j = 0; j < 16; j++) o[j] = fmaf(v.z, w[32 + j], o[j]);
                #pragma unroll
                for (int j = 0; j < 16; j++) o[j] = fmaf(v.w, w[48 + j], o[j]);
            }
            uint4 pk[2];
            unsigned* pw = (unsigned*)pk;
            #pragma unroll
            for (int q = 0; q < 8; q++) {
                __half2 h = __floats2half2_rn(o[2 * q], o[2 * q + 1]);   // unscaled
                pw[q] = *(unsigned*)&h;
            }
            uint4* hp = (uint4*)&g_hrh[r][n * 16];
            hp[0] = pk[0];
            hp[1] = pk[1];
        }
    } else {
        // ---- edge path: deg_out RED + bucket scatter (2 edges/thread) ----
        int t = (blockIdx.x - NB_T) * 256 + threadIdx.x;
        int i = t * 2;
        if (i >= E_TOT) return;
        int r, e, off;
        const void *sp, *dp;
        if (i < E_RSR)                { r = 0; e = i;                 sp = s0; dp = d0; off = 0; }
        else if (i < E_RSR + E_RTR)   { r = 1; e = i - E_RSR;         sp = s1; dp = d1; off = CAP0; }
        else                          { r = 2; e = i - E_RSR - E_RTR; sp = s2; dp = d2; off = CAP0 + CAP1; }
        int sA, sB, dA, dB;
        if (g_is64) {
            int4 sv = ldcs_i4((const char*)sp + (size_t)e * 8);
            int4 dv = ldcs_i4((const char*)dp + (size_t)e * 8);
            sA = sv.x; sB = sv.z; dA = dv.x; dB = dv.z;
        } else {
            int2 sv = ldcs_i2((const char*)sp + (size_t)e * 4);
            int2 dv = ldcs_i2((const char*)dp + (size_t)e * 4);
            sA = sv.x; sB = sv.y; dA = dv.x; dB = dv.y;
        }
        int rb = r * NN;
        atomicAdd(&g_deg_out[rb + sA], 1);
        atomicAdd(&g_deg_out[rb + sB], 1);
        int pA = atomicAdd(&g_cnt[rb + dA], 1);
        int pB = atomicAdd(&g_cnt[rb + dB], 1);
        g_ssrc[(size_t)dA * CAPT + off + pA] = (unsigned short)sA;
        g_ssrc[(size_t)dB * CAPT + off + pB] = (unsigned short)sB;
    }
}

// ---------------- scale features in place by rsqrt(deg_out) (per (rel,node) row) ----------------
__global__ void __launch_bounds__(256) k_scale() {
    int i = blockIdx.x * blockDim.x + threadIdx.x;
    if (i >= NROWS) return;
    float rv = rinv_of(__ldg(&g_deg_out[i]));
    int r = i / NN;
    int n = i - r * NN;
    uint4* hp = (uint4*)&g_hrh[r][n * 16];
    uint4 a = hp[0], b = hp[1];
    unsigned* aw = (unsigned*)&a;
    unsigned* bw = (unsigned*)&b;
    #pragma unroll
    for (int q = 0; q < 4; q++) {
        float2 f = __half22float2(*(__half2*)&aw[q]);
        __half2 h = __floats2half2_rn(f.x * rv, f.y * rv);
        aw[q] = *(unsigned*)&h;
    }
    #pragma unroll
    for (int q = 0; q < 4; q++) {
        float2 f = __half22float2(*(__half2*)&bw[q]);
        __half2 h = __floats2half2_rn(f.x * rv, f.y * rv);
        bw[q] = *(unsigned*)&h;
    }
    hp[0] = a;
    hp[1] = b;
}

// ---------------- gather layer 1 (R11 shape: 4 lanes/edge uint2, prefetch pipeline) ----------------
__global__ void __launch_bounds__(256) k_gather1(const float* __restrict__ b1,
                                                 const float* __restrict__ W2) {
    int wid = (blockIdx.x * blockDim.x + threadIdx.x) >> 5;
    if (wid >= NN) return;
    int lane = threadIdx.x & 31;
    int slot = lane >> 2, chunk = lane & 3;
    const int offs[3] = { 0, CAP0, CAP0 + CAP1 };
    int cnt[3];
    #pragma unroll
    for (int r = 0; r < 3; r++) cnt[r] = __ldg(&g_cnt[r * NN + wid]);
    const unsigned short* row = &g_ssrc[(size_t)wid * CAPT];
    float4 acc = make_float4(0.f, 0.f, 0.f, 0.f);
    #pragma unroll
    for (int r = 0; r < 3; r++) {
        int st = offs[r];
        int end = st + cnt[r];
        float w = rinv_of(cnt[r]);
        const __half* hr = g_hrh[r];
        int base = st;
        int eid = base + slot;
        int sCur = (eid < end) ? (int)__ldg(&row[eid]) : 0;
        for (; base < end; base += 8) {
            bool valid = (base + slot) < end;
            int s = sCur;
            int ne = base + 8 + slot;
            sCur = (ne < end) ? (int)__ldg(&row[ne]) : 0;   // prefetch next iter's index
            if (valid) {
                uint2 u = __ldg((const uint2*)&hr[s * 16 + chunk * 4]);
                float2 f0 = __half22float2(*(__half2*)&u.x);
                float2 f1 = __half22float2(*(__half2*)&u.y);
                acc.x = fmaf(f0.x, w, acc.x);
                acc.y = fmaf(f0.y, w, acc.y);
                acc.z = fmaf(f1.x, w, acc.z);
                acc.w = fmaf(f1.y, w, acc.w);
            }
        }
    }
    #pragma unroll
    for (int m = 16; m >= 4; m >>= 1) {
        acc.x += __shfl_xor_sync(0xffffffffu, acc.x, m);
        acc.y += __shfl_xor_sync(0xffffffffu, acc.y, m);
        acc.z += __shfl_xor_sync(0xffffffffu, acc.z, m);
        acc.w += __shfl_xor_sync(0xffffffffu, acc.w, m);
    }
    int c4 = chunk * 4;
    #pragma unroll
    for (int k = 0; k < 4; k++) {
        float bs = __ldg(&b1[c4 + k]) + __ldg(&b1[16 + c4 + k]) + __ldg(&b1[32 + c4 + k]);
        float* a = (k == 0) ? &acc.x : (k == 1) ? &acc.y : (k == 2) ? &acc.z : &acc.w;
        *a = fmaxf(*a + bs, 0.f);
    }
    #pragma unroll
    for (int r = 0; r < 3; r++) {
        const float* w2 = W2 + r * 16 + c4;
        float p = acc.x * __ldg(&w2[0]) + acc.y * __ldg(&w2[1])
                + acc.z * __ldg(&w2[2]) + acc.w * __ldg(&w2[3]);
        p += __shfl_xor_sync(0xffffffffu, p, 1);
        p += __shfl_xor_sync(0xffffffffu, p, 2);
        if (lane == r)
            g_gv[r * NN + wid] = p * rinv_of(__ldg(&g_deg_out[r * NN + wid]));
    }
}

// ---------------- gather layer 2 (pipelined) ----------------
__global__ void __launch_bounds__(256) k_gather2(float* __restrict__ out,
                                                 const float* __restrict__ b2) {
    int wid = (blockIdx.x * blockDim.x + threadIdx.x) >> 5;
    if (wid >= NN) return;
    int lane = threadIdx.x & 31;
    const int offs[3] = { 0, CAP0, CAP0 + CAP1 };
    int cnt[3];
    #pragma unroll
    for (int r = 0; r < 3; r++) cnt[r] = __ldg(&g_cnt[r * NN + wid]);
    const unsigned short* row = &g_ssrc[(size_t)wid * CAPT];
    float sum = 0.f;
    #pragma unroll
    for (int r = 0; r < 3; r++) {
        int st = offs[r];
        int end = st + cnt[r];
        float w = rinv_of(cnt[r]);
        const float* gv = &g_gv[r * NN];
        int base = st;
        int eid = base + lane;
        int sCur = (eid < end) ? (int)__ldg(&row[eid]) : 0;
        for (; base < end; base += 32) {
            bool valid = (base + lane) < end;
            int s = sCur;
            int ne = base + 32 + lane;
            sCur = (ne < end) ? (int)__ldg(&row[ne]) : 0;
            if (valid) sum = fmaf(__ldg(&gv[s]), w, sum);
        }
    }
    #pragma unroll
    for (int m = 16; m >= 1; m >>= 1)
        sum += __shfl_xor_sync(0xffffffffu, sum, m);
    if (lane == 0)
        out[wid] = sum + __ldg(&b2[0]) + __ldg(&b2[1]) + __ldg(&b2[2]);
}

// =====================================================================================
extern "C" void kernel_launch(void* const* d_in, const int* in_sizes, int n_in,
                              void* d_out, int out_size) {
    const float* x  = (const float*)d_in[0];
    const void*  s0 = d_in[1]; const void* d0 = d_in[2];
    const void*  s1 = d_in[3]; const void* d1 = d_in[4];
    const void*  s2 = d_in[5]; const void* d2 = d_in[6];
    const float* W1 = (const float*)d_in[7];
    const float* b1 = (const float*)d_in[8];
    const float* W2 = (const float*)d_in[9];
    const float* b2 = (const float*)d_in[10];
    float* out = (float*)d_out;

    k_init   <<<(NROWS + 255) / 256, 256>>>((const unsigned*)s0);               // 0
    k_pass1  <<<NB_T + NB_SCAT, 256>>>(x, W1, s0, d0, s1, d1, s2, d2);          // 1
    k_scale  <<<(NROWS + 255) / 256, 256>>>();                                  // 2
    k_gather1<<<(NN * 32 + 255) / 256, 256>>>(b1, W2);                          // 3 <- profiled
    k_gather2<<<(NN * 32 + 255) / 256, 256>>>(out, b2);                         // 4
}

// round 15
// speedup vs baseline: 1.2530x; 1.0173x over previous
#include <cuda_runtime.h>
#include <cuda_fp16.h>
#include <cstdint>

#define NN      50000
#define E_RSR   3000000
#define E_RTR   1000000
#define E_RUR   200000
#define E_TOT   4200000
#define NROWS   (3 * NN)
// padded per-(rel,dst) buckets, node-major: row base = dst*256 + OFF[r]
#define CAP0    160     // rel0 in-deg lambda=60
#define CAP1    64      // rel1 lambda=20
#define CAP2    32      // rel2 lambda=4
#define CAPT    256
#define NB_T    196     // ceil(NN/256) transform blocks in fused kernel
#define NB_SCAT ((E_TOT / 2 + 255) / 256)   // 8204 scatter blocks

// ---------------- device scratch ----------------
// Counters are zero on first use (CUDA zero-init of device globals) and are
// re-zeroed at the tail of k_gather2 each run, so every kernel_launch call
// (correctness, capture, replay) starts from clean state.
__device__ int            g_deg_out[NROWS];
__device__ int            g_cnt[NROWS];              // in-degree counters / row lengths
__device__ unsigned short g_ssrc[(size_t)NN * CAPT]; // bucketed src ids (25.6MB)
__device__ __half         g_hrh[3][NN * 16];         // fp16 features (unscaled until k_scale)
__device__ float          g_gv[NROWS];

// ---------------- helpers ----------------
__device__ __forceinline__ int4 ldcs_i4(const void* p) {
    int4 v;
    asm volatile("ld.global.cs.v4.b32 {%0,%1,%2,%3}, [%4];"
                 : "=r"(v.x), "=r"(v.y), "=r"(v.z), "=r"(v.w) : "l"(p));
    return v;
}
__device__ __forceinline__ int2 ldcs_i2(const void* p) {
    int2 v;
    asm volatile("ld.global.cs.v2.b32 {%0,%1}, [%2];" : "=r"(v.x), "=r"(v.y) : "l"(p));
    return v;
}
__device__ __forceinline__ float rinv_of(int deg) {
    return rsqrtf(fmaxf((float)deg, 1.f));
}

// ---------------- fused pass1: matmul transform (blocks [0,NB_T)) + edge pass ----------------
// transform path has NO dependency on the edge pass (stores UNSCALED fp16 features);
// scaling by rsqrt(deg_out) happens in k_scale after this kernel completes.
__global__ void __launch_bounds__(256, 6) k_pass1(
        const float* __restrict__ x, const float* __restrict__ W1,
        const void* s0, const void* d0,
        const void* s1, const void* d1,
        const void* s2, const void* d2) {
    if (blockIdx.x < NB_T) {
        // ---- matmul path: stream x in float4 chunks (low reg pressure) ----
        __shared__ float sW[3 * 32 * 16];
        for (int j = threadIdx.x; j < 1536; j += 256) sW[j] = W1[j];
        __syncthreads();
        int n = blockIdx.x * 256 + threadIdx.x;
        if (n >= NN) return;
        const float4* xp = (const float4*)(x + (size_t)n * 32);
        #pragma unroll 1
        for (int r = 0; r < 3; r++) {
            float o[16];
            #pragma unroll
            for (int j = 0; j < 16; j++) o[j] = 0.f;
            const float* wr = &sW[r * 512];
            #pragma unroll
            for (int q = 0; q < 8; q++) {
                float4 v = __ldg(&xp[q]);           // L1-hot after first relation
                const float* w = wr + q * 64;
                #pragma unroll
                for (int j = 0; j < 16; j++) o[j] = fmaf(v.x, w[j], o[j]);
                #pragma unroll
                for (int j = 0; j < 16; j++) o[j] = fmaf(v.y, w[16 + j], o[j]);
                #pragma unroll
                for (int j = 0; j < 16; j++) o[j] = fmaf(v.z, w[32 + j], o[j]);
                #pragma unroll
                for (int j = 0; j < 16; j++) o[j] = fmaf(v.w, w[48 + j], o[j]);
            }
            uint4 pk[2];
            unsigned* pw = (unsigned*)pk;
            #pragma unroll
            for (int q = 0; q < 8; q++) {
                __half2 h = __floats2half2_rn(o[2 * q], o[2 * q + 1]);   // unscaled
                pw[q] = *(unsigned*)&h;
            }
            uint4* hp = (uint4*)&g_hrh[r][n * 16];
            hp[0] = pk[0];
            hp[1] = pk[1];
        }
    } else {
        // ---- edge path: inline dtype probe + deg_out RED + bucket scatter (2 edges/thread) ----
        // probe: first 32B of s0 broadcast-loaded; odd 32-bit words all zero <=> int64 indices
        const int4* pb = (const int4*)s0;
        int4 p0 = __ldg(pb);
        int4 p1 = __ldg(pb + 1);
        bool is64 = ((p0.y | p0.w | p1.y | p1.w) == 0);
        int t = (blockIdx.x - NB_T) * 256 + threadIdx.x;
        int i = t * 2;
        if (i >= E_TOT) return;
        int r, e, off;
        const void *sp, *dp;
        if (i < E_RSR)                { r = 0; e = i;                 sp = s0; dp = d0; off = 0; }
        else if (i < E_RSR + E_RTR)   { r = 1; e = i - E_RSR;         sp = s1; dp = d1; off = CAP0; }
        else                          { r = 2; e = i - E_RSR - E_RTR; sp = s2; dp = d2; off = CAP0 + CAP1; }
        int sA, sB, dA, dB;
        if (is64) {
            int4 sv = ldcs_i4((const char*)sp + (size_t)e * 8);
            int4 dv = ldcs_i4((const char*)dp + (size_t)e * 8);
            sA = sv.x; sB = sv.z; dA = dv.x; dB = dv.z;
        } else {
            int2 sv = ldcs_i2((const char*)sp + (size_t)e * 4);
            int2 dv = ldcs_i2((const char*)dp + (size_t)e * 4);
            sA = sv.x; sB = sv.y; dA = dv.x; dB = dv.y;
        }
        int rb = r * NN;
        atomicAdd(&g_deg_out[rb + sA], 1);
        atomicAdd(&g_deg_out[rb + sB], 1);
        int pA = atomicAdd(&g_cnt[rb + dA], 1);
        int pB = atomicAdd(&g_cnt[rb + dB], 1);
        g_ssrc[(size_t)dA * CAPT + off + pA] = (unsigned short)sA;
        g_ssrc[(size_t)dB * CAPT + off + pB] = (unsigned short)sB;
    }
}

// ---------------- scale features in place by rsqrt(deg_out) (per (rel,node) row) ----------------
__global__ void __launch_bounds__(256) k_scale() {
    int i = blockIdx.x * blockDim.x + threadIdx.x;
    if (i >= NROWS) return;
    float rv = rinv_of(__ldg(&g_deg_out[i]));
    int r = i / NN;
    int n = i - r * NN;
    uint4* hp = (uint4*)&g_hrh[r][n * 16];
    uint4 a = hp[0], b = hp[1];
    unsigned* aw = (unsigned*)&a;
    unsigned* bw = (unsigned*)&b;
    #pragma unroll
    for (int q = 0; q < 4; q++) {
        float2 f = __half22float2(*(__half2*)&aw[q]);
        __half2 h = __floats2half2_rn(f.x * rv, f.y * rv);
        aw[q] = *(unsigned*)&h;
    }
    #pragma unroll
    for (int q = 0; q < 4; q++) {
        float2 f = __half22float2(*(__half2*)&bw[q]);
        __half2 h = __floats2half2_rn(f.x * rv, f.y * rv);
        bw[q] = *(unsigned*)&h;
    }
    hp[0] = a;
    hp[1] = b;
}

// ---------------- gather layer 1 (R11 shape: 4 lanes/edge uint2, prefetch pipeline) ----------------
__global__ void __launch_bounds__(256) k_gather1(const float* __restrict__ b1,
                                                 const float* __restrict__ W2) {
    int wid = (blockIdx.x * blockDim.x + threadIdx.x) >> 5;
    if (wid >= NN) return;
    int lane = threadIdx.x & 31;
    int slot = lane >> 2, chunk = lane & 3;
    const int offs[3] = { 0, CAP0, CAP0 + CAP1 };
    int cnt[3];
    #pragma unroll
    for (int r = 0; r < 3; r++) cnt[r] = __ldg(&g_cnt[r * NN + wid]);
    const unsigned short* row = &g_ssrc[(size_t)wid * CAPT];
    float4 acc = make_float4(0.f, 0.f, 0.f, 0.f);
    #pragma unroll
    for (int r = 0; r < 3; r++) {
        int st = offs[r];
        int end = st + cnt[r];
        float w = rinv_of(cnt[r]);
        const __half* hr = g_hrh[r];
        int base = st;
        int eid = base + slot;
        int sCur = (eid < end) ? (int)__ldg(&row[eid]) : 0;
        for (; base < end; base += 8) {
            bool valid = (base + slot) < end;
            int s = sCur;
            int ne = base + 8 + slot;
            sCur = (ne < end) ? (int)__ldg(&row[ne]) : 0;   // prefetch next iter's index
            if (valid) {
                uint2 u = __ldg((const uint2*)&hr[s * 16 + chunk * 4]);
                float2 f0 = __half22float2(*(__half2*)&u.x);
                float2 f1 = __half22float2(*(__half2*)&u.y);
                acc.x = fmaf(f0.x, w, acc.x);
                acc.y = fmaf(f0.y, w, acc.y);
                acc.z = fmaf(f1.x, w, acc.z);
                acc.w = fmaf(f1.y, w, acc.w);
            }
        }
    }
    #pragma unroll
    for (int m = 16; m >= 4; m >>= 1) {
        acc.x += __shfl_xor_sync(0xffffffffu, acc.x, m);
        acc.y += __shfl_xor_sync(0xffffffffu, acc.y, m);
        acc.z += __shfl_xor_sync(0xffffffffu, acc.z, m);
        acc.w += __shfl_xor_sync(0xffffffffu, acc.w, m);
    }
    int c4 = chunk * 4;
    #pragma unroll
    for (int k = 0; k < 4; k++) {
        float bs = __ldg(&b1[c4 + k]) + __ldg(&b1[16 + c4 + k]) + __ldg(&b1[32 + c4 + k]);
        float* a = (k == 0) ? &acc.x : (k == 1) ? &acc.y : (k == 2) ? &acc.z : &acc.w;
        *a = fmaxf(*a + bs, 0.f);
    }
    #pragma unroll
    for (int r = 0; r < 3; r++) {
        const float* w2 = W2 + r * 16 + c4;
        float p = acc.x * __ldg(&w2[0]) + acc.y * __ldg(&w2[1])
                + acc.z * __ldg(&w2[2]) + acc.w * __ldg(&w2[3]);
        p += __shfl_xor_sync(0xffffffffu, p, 1);
        p += __shfl_xor_sync(0xffffffffu, p, 2);
        if (lane == r)
            g_gv[r * NN + wid] = p * rinv_of(__ldg(&g_deg_out[r * NN + wid]));
    }
}

// ---------------- gather layer 2 (pipelined) + counter cleanup for next replay ----------------
__global__ void __launch_bounds__(256) k_gather2(float* __restrict__ out,
                                                 const float* __restrict__ b2) {
    int wid = (blockIdx.x * blockDim.x + threadIdx.x) >> 5;
    if (wid >= NN) return;
    int lane = threadIdx.x & 31;
    const int offs[3] = { 0, CAP0, CAP0 + CAP1 };
    int cnt[3];
    #pragma unroll
    for (int r = 0; r < 3; r++) cnt[r] = __ldg(&g_cnt[r * NN + wid]);
    const unsigned short* row = &g_ssrc[(size_t)wid * CAPT];
    float sum = 0.f;
    #pragma unroll
    for (int r = 0; r < 3; r++) {
        int st = offs[r];
        int end = st + cnt[r];
        float w = rinv_of(cnt[r]);
        const float* gv = &g_gv[r * NN];
        int base = st;
        int eid = base + lane;
        int sCur = (eid < end) ? (int)__ldg(&row[eid]) : 0;
        for (; base < end; base += 32) {
            bool valid = (base + lane) < end;
            int s = sCur;
            int ne = base + 32 + lane;
            sCur = (ne < end) ? (int)__ldg(&row[ne]) : 0;
            if (valid) sum = fmaf(__ldg(&gv[s]), w, sum);
        }
    }
    #pragma unroll
    for (int m = 16; m >= 1; m >>= 1)
        sum += __shfl_xor_sync(0xffffffffu, sum, m);
    if (lane == 0)
        out[wid] = sum + __ldg(&b2[0]) + __ldg(&b2[1]) + __ldg(&b2[2]);
    // zero this node's counters for the next graph replay (only this warp ever
    // reads them this run; gather1 already finished)
    if (lane < 3) {
        g_cnt[lane * NN + wid] = 0;
        g_deg_out[lane * NN + wid] = 0;
    }
}

// =====================================================================================
extern "C" void kernel_launch(void* const* d_in, const int* in_sizes, int n_in,
                              void* d_out, int out_size) {
    const float* x  = (const float*)d_in[0];
    const void*  s0 = d_in[1]; const void* d0 = d_in[2];
    const void*  s1 = d_in[3]; const void* d1 = d_in[4];
    const void*  s2 = d_in[5]; const void* d2 = d_in[6];
    const float* W1 = (const float*)d_in[7];
    const float* b1 = (const float*)d_in[8];
    const float* W2 = (const float*)d_in[9];
    const float* b2 = (const float*)d_in[10];
    float* out = (float*)d_out;

    k_pass1  <<<NB_T + NB_SCAT, 256>>>(x, W1, s0, d0, s1, d1, s2, d2);          // 0
    k_scale  <<<(NROWS + 255) / 256, 256>>>();                                  // 1
    k_gather1<<<(NN * 32 + 255) / 256, 256>>>(b1, W2);                          // 2
    k_gather2<<<(NN * 32 + 255) / 256, 256>>>(out, b2);                         // 3 <- profiled
}

// round 16
// speedup vs baseline: 1.3347x; 1.0653x over previous
#include <cuda_runtime.h>
#include <cuda_fp16.h>
#include <cstdint>

#define NN      50000
#define E_RSR   3000000
#define E_RTR   1000000
#define E_RUR   200000
#define E_TOT   4200000
#define NROWS   (3 * NN)
// padded per-(rel,dst) buckets, node-major: row base = dst*256 + OFF[r]
// boundaries (0,160,224) are multiples of 8 -> an 8-slot lane group never spans relations
#define CAP0    160     // rel0 in-deg lambda=60
#define CAP1    64      // rel1 lambda=20
#define CAP2    32      // rel2 lambda=4
#define CAPT    256
#define NB_T    196     // ceil(NN/256) transform blocks in fused kernel
#define NB_SCAT ((E_TOT / 2 + 255) / 256)   // 8204 scatter blocks

// ---------------- device scratch ----------------
// Counters are zero on first use (CUDA zero-init) and re-zeroed at the tail of
// k_gather2 each run, so every call starts from clean state.
__device__ int            g_deg_out[NROWS];
__device__ int            g_cnt[NROWS];              // in-degree counters / row lengths
__device__ unsigned short g_ssrc[(size_t)NN * CAPT]; // bucketed src ids (25.6MB)
__device__ __half         g_hrh[3][NN * 16];         // fp16 features (unscaled until k_scale)
__device__ float          g_gv[NROWS];

// ---------------- helpers ----------------
__device__ __forceinline__ int4 ldcs_i4(const void* p) {
    int4 v;
    asm volatile("ld.global.cs.v4.b32 {%0,%1,%2,%3}, [%4];"
                 : "=r"(v.x), "=r"(v.y), "=r"(v.z), "=r"(v.w) : "l"(p));
    return v;
}
__device__ __forceinline__ int2 ldcs_i2(const void* p) {
    int2 v;
    asm volatile("ld.global.cs.v2.b32 {%0,%1}, [%2];" : "=r"(v.x), "=r"(v.y) : "l"(p));
    return v;
}
__device__ __forceinline__ float rinv_of(int deg) {
    return rsqrtf(fmaxf((float)deg, 1.f));
}

// ---------------- fused pass1: matmul transform (blocks [0,NB_T)) + edge pass ----------------
__global__ void __launch_bounds__(256, 6) k_pass1(
        const float* __restrict__ x, const float* __restrict__ W1,
        const void* s0, const void* d0,
        const void* s1, const void* d1,
        const void* s2, const void* d2) {
    if (blockIdx.x < NB_T) {
        // ---- matmul path: stream x in float4 chunks (low reg pressure) ----
        __shared__ float sW[3 * 32 * 16];
        for (int j = threadIdx.x; j < 1536; j += 256) sW[j] = W1[j];
        __syncthreads();
        int n = blockIdx.x * 256 + threadIdx.x;
        if (n >= NN) return;
        const float4* xp = (const float4*)(x + (size_t)n * 32);
        #pragma unroll 1
        for (int r = 0; r < 3; r++) {
            float o[16];
            #pragma unroll
            for (int j = 0; j < 16; j++) o[j] = 0.f;
            const float* wr = &sW[r * 512];
            #pragma unroll
            for (int q = 0; q < 8; q++) {
                float4 v = __ldg(&xp[q]);           // L1-hot after first relation
                const float* w = wr + q * 64;
                #pragma unroll
                for (int j = 0; j < 16; j++) o[j] = fmaf(v.x, w[j], o[j]);
                #pragma unroll
                for (int j = 0; j < 16; j++) o[j] = fmaf(v.y, w[16 + j], o[j]);
                #pragma unroll
                for (int j = 0; j < 16; j++) o[j] = fmaf(v.z, w[32 + j], o[j]);
                #pragma unroll
                for (int j = 0; j < 16; j++) o[j] = fmaf(v.w, w[48 + j], o[j]);
            }
            uint4 pk[2];
            unsigned* pw = (unsigned*)pk;
            #pragma unroll
            for (int q = 0; q < 8; q++) {
                __half2 h = __floats2half2_rn(o[2 * q], o[2 * q + 1]);   // unscaled
                pw[q] = *(unsigned*)&h;
            }
            uint4* hp = (uint4*)&g_hrh[r][n * 16];
            hp[0] = pk[0];
            hp[1] = pk[1];
        }
    } else {
        // ---- edge path: inline dtype probe + deg_out RED + bucket scatter ----
        const int4* pb = (const int4*)s0;
        int4 p0 = __ldg(pb);
        int4 p1 = __ldg(pb + 1);
        bool is64 = ((p0.y | p0.w | p1.y | p1.w) == 0);
        int t = (blockIdx.x - NB_T) * 256 + threadIdx.x;
        int i = t * 2;
        if (i >= E_TOT) return;
        int r, e, off;
        const void *sp, *dp;
        if (i < E_RSR)                { r = 0; e = i;                 sp = s0; dp = d0; off = 0; }
        else if (i < E_RSR + E_RTR)   { r = 1; e = i - E_RSR;         sp = s1; dp = d1; off = CAP0; }
        else                          { r = 2; e = i - E_RSR - E_RTR; sp = s2; dp = d2; off = CAP0 + CAP1; }
        int sA, sB, dA, dB;
        if (is64) {
            int4 sv = ldcs_i4((const char*)sp + (size_t)e * 8);
            int4 dv = ldcs_i4((const char*)dp + (size_t)e * 8);
            sA = sv.x; sB = sv.z; dA = dv.x; dB = dv.z;
        } else {
            int2 sv = ldcs_i2((const char*)sp + (size_t)e * 4);
            int2 dv = ldcs_i2((const char*)dp + (size_t)e * 4);
            sA = sv.x; sB = sv.y; dA = dv.x; dB = dv.y;
        }
        int rb = r * NN;
        atomicAdd(&g_deg_out[rb + sA], 1);
        atomicAdd(&g_deg_out[rb + sB], 1);
        int pA = atomicAdd(&g_cnt[rb + dA], 1);
        int pB = atomicAdd(&g_cnt[rb + dB], 1);
        g_ssrc[(size_t)dA * CAPT + off + pA] = (unsigned short)sA;
        g_ssrc[(size_t)dB * CAPT + off + pB] = (unsigned short)sB;
    }
}

// ---------------- scale features in place by rsqrt(deg_out) ----------------
__global__ void __launch_bounds__(256) k_scale() {
    int i = blockIdx.x * blockDim.x + threadIdx.x;
    if (i >= NROWS) return;
    float rv = rinv_of(__ldg(&g_deg_out[i]));
    int r = i / NN;
    int n = i - r * NN;
    uint4* hp = (uint4*)&g_hrh[r][n * 16];
    uint4 a = hp[0], b = hp[1];
    unsigned* aw = (unsigned*)&a;
    unsigned* bw = (unsigned*)&b;
    #pragma unroll
    for (int q = 0; q < 4; q++) {
        float2 f = __half22float2(*(__half2*)&aw[q]);
        __half2 h = __floats2half2_rn(f.x * rv, f.y * rv);
        aw[q] = *(unsigned*)&h;
    }
    #pragma unroll
    for (int q = 0; q < 4; q++) {
        float2 f = __half22float2(*(__half2*)&bw[q]);
        __half2 h = __floats2half2_rn(f.x * rv, f.y * rv);
        bw[q] = *(unsigned*)&h;
    }
    hp[0] = a;
    hp[1] = b;
}

// ---------------- gather layer 1: smem-staged indices, 4 lanes/edge uint2 ----------------
__global__ void __launch_bounds__(256) k_gather1(const float* __restrict__ b1,
                                                 const float* __restrict__ W2) {
    __shared__ unsigned short srow[8][CAPT];        // 4KB: one 512B row per warp
    int wlocal = threadIdx.x >> 5;
    int wid = (blockIdx.x * blockDim.x + threadIdx.x) >> 5;
    if (wid >= NN) return;
    int lane = threadIdx.x & 31;
    int slot = lane >> 2, chunk = lane & 3;
    const int offs[3] = { 0, CAP0, CAP0 + CAP1 };
    int cnt[3];
    #pragma unroll
    for (int r = 0; r < 3; r++) cnt[r] = __ldg(&g_cnt[r * NN + wid]);
    // stage whole index row to smem: one uint4 per lane (coalesced 512B/warp)
    const uint4* row4 = (const uint4*)&g_ssrc[(size_t)wid * CAPT];
    ((uint4*)srow[wlocal])[lane] = __ldg(&row4[lane]);
    __syncwarp();
    const unsigned short* row = srow[wlocal];
    float4 acc = make_float4(0.f, 0.f, 0.f, 0.f);
    #pragma unroll
    for (int r = 0; r < 3; r++) {
        int st = offs[r];
        int end = st + cnt[r];
        float w = rinv_of(cnt[r]);
        const __half* hr = g_hrh[r];
        for (int base = st; base < end; base += 8) {
            int eid = base + slot;
            if (eid < end) {
                int s = row[eid];                               // LDS, broadcast x4
                uint2 u = __ldg((const uint2*)&hr[s * 16 + chunk * 4]);
                float2 f0 = __half22float2(*(__half2*)&u.x);
                float2 f1 = __half22float2(*(__half2*)&u.y);
                acc.x = fmaf(f0.x, w, acc.x);
                acc.y = fmaf(f0.y, w, acc.y);
                acc.z = fmaf(f1.x, w, acc.z);
                acc.w = fmaf(f1.y, w, acc.w);
            }
        }
    }
    #pragma unroll
    for (int m = 16; m >= 4; m >>= 1) {
        acc.x += __shfl_xor_sync(0xffffffffu, acc.x, m);
        acc.y += __shfl_xor_sync(0xffffffffu, acc.y, m);
        acc.z += __shfl_xor_sync(0xffffffffu, acc.z, m);
        acc.w += __shfl_xor_sync(0xffffffffu, acc.w, m);
    }
    int c4 = chunk * 4;
    #pragma unroll
    for (int k = 0; k < 4; k++) {
        float bs = __ldg(&b1[c4 + k]) + __ldg(&b1[16 + c4 + k]) + __ldg(&b1[32 + c4 + k]);
        float* a = (k == 0) ? &acc.x : (k == 1) ? &acc.y : (k == 2) ? &acc.z : &acc.w;
        *a = fmaxf(*a + bs, 0.f);
    }
    #pragma unroll
    for (int r = 0; r < 3; r++) {
        const float* w2 = W2 + r * 16 + c4;
        float p = acc.x * __ldg(&w2[0]) + acc.y * __ldg(&w2[1])
                + acc.z * __ldg(&w2[2]) + acc.w * __ldg(&w2[3]);
        p += __shfl_xor_sync(0xffffffffu, p, 1);
        p += __shfl_xor_sync(0xffffffffu, p, 2);
        if (lane == r)
            g_gv[r * NN + wid] = p * rinv_of(__ldg(&g_deg_out[r * NN + wid]));
    }
}

// ---------------- gather layer 2: per-lane fixed region, 8 unrolled gathers (MLP=8) ----------------
// lane L owns slots [8L, 8L+8); region boundaries (160,224) are multiples of 8 so each
// lane is entirely in one relation: lanes 0-19 -> r0, 20-27 -> r1, 28-31 -> r2.
__global__ void __launch_bounds__(256) k_gather2(float* __restrict__ out,
                                                 const float* __restrict__ b2) {
    int wid = (blockIdx.x * blockDim.x + threadIdx.x) >> 5;
    if (wid >= NN) return;
    int lane = threadIdx.x & 31;
    int r = (lane >= 20) + (lane >= 28);
    int offr = (r == 0) ? 0 : ((r == 1) ? CAP0 : (CAP0 + CAP1));
    int cntr = __ldg(&g_cnt[r * NN + wid]);
    float w = rinv_of(cntr);
    int base_local = lane * 8 - offr;               // >= 0 by construction
    // one 16B load covers this lane's 8 slots (coalesced 512B/warp)
    uint4 u = __ldg((const uint4*)&g_ssrc[(size_t)wid * CAPT] + lane);
    int s[8];
    s[0] = u.x & 0xFFFF;  s[1] = (int)((unsigned)u.x >> 16);
    s[2] = u.y & 0xFFFF;  s[3] = (int)((unsigned)u.y >> 16);
    s[4] = u.z & 0xFFFF;  s[5] = (int)((unsigned)u.z >> 16);
    s[6] = u.w & 0xFFFF;  s[7] = (int)((unsigned)u.w >> 16);
    const float* gv = &g_gv[r * NN];
    float sum = 0.f;
    #pragma unroll
    for (int k = 0; k < 8; k++) {
        if (base_local + k < cntr)
            sum += __ldg(&gv[s[k]]);                // 8 independent gathers in flight
    }
    sum *= w;
    #pragma unroll
    for (int m = 16; m >= 1; m >>= 1)
        sum += __shfl_xor_sync(0xffffffffu, sum, m);
    if (lane == 0)
        out[wid] = sum + __ldg(&b2[0]) + __ldg(&b2[1]) + __ldg(&b2[2]);
    // zero this node's counters for the next graph replay
    if (lane < 3) {
        g_cnt[lane * NN + wid] = 0;
        g_deg_out[lane * NN + wid] = 0;
    }
}

// =====================================================================================
extern "C" void kernel_launch(void* const* d_in, const int* in_sizes, int n_in,
                              void* d_out, int out_size) {
    const float* x  = (const float*)d_in[0];
    const void*  s0 = d_in[1]; const void* d0 = d_in[2];
    const void*  s1 = d_in[3]; const void* d1 = d_in[4];
    const void*  s2 = d_in[5]; const void* d2 = d_in[6];
    const float* W1 = (const float*)d_in[7];
    const float* b1 = (const float*)d_in[8];
    const float* W2 = (const float*)d_in[9];
    const float* b2 = (const float*)d_in[10];
    float* out = (float*)d_out;

    k_pass1  <<<NB_T + NB_SCAT, 256>>>(x, W1, s0, d0, s1, d1, s2, d2);          // 0
    k_scale  <<<(NROWS + 255) / 256, 256>>>();                                  // 1
    k_gather1<<<(NN * 32 + 255) / 256, 256>>>(b1, W2);                          // 2
    k_gather2<<<(NN * 32 + 255) / 256, 256>>>(out, b2);                         // 3 <- profiled
}